// round 10
// baseline (speedup 1.0000x reference)
#include <cuda_runtime.h>

#define N_Q    4
#define DIM    16
#define COLS   512
#define RPW    8                      // rows per warp (GEMV phase)
#define BLOCK  256
#define RPB    (BLOCK / 32 * RPW)     // 64 rows per block

__global__ void __launch_bounds__(BLOCK) qnet_kernel(
    const float* __restrict__ x,       // [B, 512]
    const float* __restrict__ pre_w,   // [4, 512]
    const float* __restrict__ pre_b,   // [4]
    const float* __restrict__ u3p,     // [4, 3]
    const float* __restrict__ post_w,  // [2, 4]
    const float* __restrict__ post_b,  // [2]
    float* __restrict__ out,           // [B, 2]
    int B)
{
    __shared__ float4 wsh[N_Q * (COLS / 4)];   // 8 KB: pre_w
    __shared__ float  pre_sh[RPB * N_Q];       // 1 KB: GEMV results

    const int tid  = threadIdx.x;
    const int wib  = tid >> 5;                 // warp in block
    const int lane = tid & 31;
    const int blockRow0 = blockIdx.x * RPB;
    const int row0 = blockRow0 + wib * RPW;

    #pragma unroll
    for (int i = tid; i < N_Q * (COLS / 4); i += BLOCK)
        wsh[i] = reinterpret_cast<const float4*>(pre_w)[i];
    __syncthreads();

    const float4* __restrict__ x4 = reinterpret_cast<const float4*>(x);

    // ---------------- GEMV: 8 rows per warp, lane = column group ----------------
    float w[32];   // value index i = r*4 + j
    {
        float acc[RPW][N_Q];
        #pragma unroll
        for (int r = 0; r < RPW; r++)
            #pragma unroll
            for (int j = 0; j < N_Q; j++) acc[r][j] = 0.f;

        #pragma unroll
        for (int k = 0; k < 4; k++) {
            const int c4 = lane + 32 * k;
            float4 w0 = wsh[0 * 128 + c4];
            float4 w1 = wsh[1 * 128 + c4];
            float4 w2 = wsh[2 * 128 + c4];
            float4 w3 = wsh[3 * 128 + c4];
            #pragma unroll
            for (int r = 0; r < RPW; r++) {
                int gr = row0 + r;
                if (gr < B) {
                    float4 xv = x4[(size_t)gr * 128 + c4];
                    acc[r][0] += xv.x * w0.x + xv.y * w0.y + xv.z * w0.z + xv.w * w0.w;
                    acc[r][1] += xv.x * w1.x + xv.y * w1.y + xv.z * w1.z + xv.w * w1.w;
                    acc[r][2] += xv.x * w2.x + xv.y * w2.y + xv.z * w2.z + xv.w * w2.w;
                    acc[r][3] += xv.x * w3.x + xv.y * w3.y + xv.z * w3.z + xv.w * w3.w;
                }
            }
        }
        #pragma unroll
        for (int r = 0; r < RPW; r++)
            #pragma unroll
            for (int j = 0; j < N_Q; j++) w[r * 4 + j] = acc[r][j];
    }

    // ---- distributed butterfly reduce: 31 shfl; lane l ends owning sum of index l ----
    #pragma unroll
    for (int m = 16; m >= 1; m >>= 1) {
        #pragma unroll
        for (int k = 0; k < m; k++) {
            float lo = w[k], hi = w[k + m];
            float send = (lane & m) ? lo : hi;
            float recv = __shfl_xor_sync(0xFFFFFFFFu, send, m);
            w[k] = ((lane & m) ? hi : lo) + recv;
        }
    }
    // lane l holds value for (row = row0 + (l>>2), feat = l&3) -> contiguous STS
    pre_sh[wib * 32 + lane] = w[0];
    __syncthreads();

    // ---------------- circuit: first 64 threads, one full row per lane ----------------
    if (tid >= RPB) return;
    const int row = blockRow0 + tid;
    if (row >= B) return;

    float4 f = reinterpret_cast<const float4*>(pre_sh)[tid];
    float fin[N_Q] = {f.x, f.y, f.z, f.w};

    float ry[N_Q], rz[N_Q];
    #pragma unroll
    for (int k = 0; k < N_Q; k++) {
        float p = (fin[k] + __ldg(&pre_b[k])) * 0.1f;
        float t;
        asm("tanh.approx.f32 %0, %1;" : "=f"(t) : "f"(p));
        float qin = t * 1.57079632679489662f;
        ry[k] = atanf(qin);
        rz[k] = atanf(qin * qin);
    }

    // ---- H on |0000>: uniform real 1/4; RY keeps state real ----
    float r[DIM];
    #pragma unroll
    for (int i = 0; i < DIM; i++) r[i] = 0.25f;
    #pragma unroll
    for (int q = 0; q < N_Q; q++) {
        float s, c;
        __sincosf(0.5f * ry[q], &s, &c);
        const int m = 8 >> q;   // q=0 is MSB
        #pragma unroll
        for (int xx = 0; xx < DIM; xx++) {
            if (!(xx & m)) {
                float a = r[xx], b = r[xx | m];
                r[xx]     = c * a - s * b;
                r[xx | m] = s * a + c * b;
            }
        }
    }

    // ---- RZ: build 16 phases as products of 4 half-angle exponentials ----
    // phase(xx) = prod_q e^{ +- i rz[q]/2 }, bit=1 -> +, bit=0 -> -
    float pr[DIM], pi[DIM];
    pr[0] = 1.f; pi[0] = 0.f;
    #pragma unroll
    for (int q = 0; q < N_Q; q++) {
        float ss, cc;
        __sincosf(0.5f * rz[q], &ss, &cc);
        const int n = 1 << q;
        #pragma unroll
        for (int t = n - 1; t >= 0; t--) {
            float a = pr[t], b = pi[t];
            pr[2 * t + 1] = a * cc - b * ss;   // bit q = 1: *(cc + i ss)
            pi[2 * t + 1] = a * ss + b * cc;
            pr[2 * t]     = a * cc + b * ss;   // bit q = 0: *(cc - i ss)
            pi[2 * t]     = b * cc - a * ss;
        }
    }
    float re[DIM], im[DIM];
    #pragma unroll
    for (int xx = 0; xx < DIM; xx++) {
        re[xx] = r[xx] * pr[xx];
        im[xx] = r[xx] * pi[xx];
    }

    // ---- CNOT rings: compile-time permutation ----
    #define DO_CNOT(cq, tq) { \
        const int cm = 8 >> (cq), tm = 8 >> (tq); \
        _Pragma("unroll") \
        for (int xx = 0; xx < DIM; xx++) { \
            if ((xx & cm) && !(xx & tm)) { \
                int yy = xx ^ tm; \
                float t0 = re[xx]; re[xx] = re[yy]; re[yy] = t0; \
                float t1 = im[xx]; im[xx] = im[yy]; im[yy] = t1; \
            } \
        } }
    DO_CNOT(0, 1); DO_CNOT(1, 2); DO_CNOT(2, 3); DO_CNOT(3, 0);
    DO_CNOT(0, 2); DO_CNOT(1, 3); DO_CNOT(2, 0); DO_CNOT(3, 1);
    #undef DO_CNOT

    // ---- U3 layer ----
    #pragma unroll
    for (int q = 0; q < N_Q; q++) {
        float th = __ldg(&u3p[q * 3 + 0]);
        float ph = __ldg(&u3p[q * 3 + 1]);
        float la = __ldg(&u3p[q * 3 + 2]);
        float st, ct; __sincosf(0.5f * th, &st, &ct);
        float sl, cl; __sincosf(la, &sl, &cl);
        float sf, cf; __sincosf(ph, &sf, &cf);
        float cpl = cf * cl - sf * sl, spl = sf * cl + cf * sl;
        float m01r = -cl * st, m01i = -sl * st;
        float m10r =  cf * st, m10i =  sf * st;
        float m11r = cpl * ct, m11i = spl * ct;
        const int m = 8 >> q;
        #pragma unroll
        for (int xx = 0; xx < DIM; xx++) {
            if (!(xx & m)) {
                int yy = xx | m;
                float ar = re[xx], ai = im[xx];
                float br = re[yy], bi = im[yy];
                re[xx] = ct * ar + m01r * br - m01i * bi;
                im[xx] = ct * ai + m01r * bi + m01i * br;
                re[yy] = m10r * ar - m10i * ai + m11r * br - m11i * bi;
                im[yy] = m10i * ar + m10r * ai + m11i * br + m11r * bi;
            }
        }
    }

    // ---- Z expectations + head ----
    float e[N_Q] = {0.f, 0.f, 0.f, 0.f};
    #pragma unroll
    for (int xx = 0; xx < DIM; xx++) {
        float p = re[xx] * re[xx] + im[xx] * im[xx];
        #pragma unroll
        for (int q = 0; q < N_Q; q++)
            e[q] += ((xx >> (3 - q)) & 1) ? -p : p;
    }
    float o0 = __ldg(&post_b[0]);
    float o1 = __ldg(&post_b[1]);
    #pragma unroll
    for (int k = 0; k < N_Q; k++) {
        o0 += e[k] * __ldg(&post_w[k]);
        o1 += e[k] * __ldg(&post_w[N_Q + k]);
    }
    reinterpret_cast<float2*>(out)[row] = make_float2(o0, o1);
}

extern "C" void kernel_launch(void* const* d_in, const int* in_sizes, int n_in,
                              void* d_out, int out_size)
{
    const float* x      = (const float*)d_in[0];
    const float* pre_w  = (const float*)d_in[1];
    const float* pre_b  = (const float*)d_in[2];
    const float* u3p    = (const float*)d_in[3];
    const float* post_w = (const float*)d_in[4];
    const float* post_b = (const float*)d_in[5];
    float* out = (float*)d_out;

    int B = in_sizes[0] / COLS;
    int grid = (B + RPB - 1) / RPB;
    qnet_kernel<<<grid, BLOCK>>>(x, pre_w, pre_b, u3p, post_w, post_b, out, B);
}

// round 13
// speedup vs baseline: 1.3636x; 1.3636x over previous
#include <cuda_runtime.h>

#define N_Q    4
#define DIM    16
#define COLS   512
#define MAXB   32768
#define RPW    4          // rows per warp (GEMV)
#define BLOCK  256

__device__ float g_pre[MAXB * N_Q];   // GEMV output scratch [B,4]

// ---------------------------------------------------------------------------
// Kernel 1: GEMV  pre[B,4] = x[B,512] @ pre_w[4,512]^T     (lean, high-occ)
// ---------------------------------------------------------------------------
__global__ void __launch_bounds__(BLOCK) gemv_kernel(
    const float* __restrict__ x,
    const float* __restrict__ pre_w,
    int B)
{
    __shared__ float4 wsh[N_Q * (COLS / 4)];   // 8 KB

    const int tid = threadIdx.x;
    #pragma unroll
    for (int i = tid; i < N_Q * (COLS / 4); i += BLOCK)
        wsh[i] = reinterpret_cast<const float4*>(pre_w)[i];
    __syncthreads();

    const int warp = (blockIdx.x * BLOCK + tid) >> 5;
    const int lane = tid & 31;
    const int row0 = warp * RPW;
    if (row0 >= B) return;

    const float4* __restrict__ x4 = reinterpret_cast<const float4*>(x);

    float acc[RPW][N_Q];
    #pragma unroll
    for (int r = 0; r < RPW; r++)
        #pragma unroll
        for (int j = 0; j < N_Q; j++) acc[r][j] = 0.f;

    #pragma unroll
    for (int k = 0; k < 4; k++) {
        const int c4 = lane + 32 * k;
        // issue all row loads first -> MLP = RPW within the iteration
        float4 xv[RPW];
        #pragma unroll
        for (int r = 0; r < RPW; r++) {
            int gr = row0 + r;
            xv[r] = x4[(size_t)(gr < B ? gr : B - 1) * 128 + c4];
        }
        float4 w0 = wsh[0 * 128 + c4];
        float4 w1 = wsh[1 * 128 + c4];
        float4 w2 = wsh[2 * 128 + c4];
        float4 w3 = wsh[3 * 128 + c4];
        #pragma unroll
        for (int r = 0; r < RPW; r++) {
            acc[r][0] += xv[r].x * w0.x + xv[r].y * w0.y + xv[r].z * w0.z + xv[r].w * w0.w;
            acc[r][1] += xv[r].x * w1.x + xv[r].y * w1.y + xv[r].z * w1.z + xv[r].w * w1.w;
            acc[r][2] += xv[r].x * w2.x + xv[r].y * w2.y + xv[r].z * w2.z + xv[r].w * w2.w;
            acc[r][3] += xv[r].x * w3.x + xv[r].y * w3.y + xv[r].z * w3.z + xv[r].w * w3.w;
        }
    }

    // reduce each of the 16 (r,j) sums across lanes; lane (r*4+j) keeps it
    float val = 0.f;
    #pragma unroll
    for (int r = 0; r < RPW; r++)
        #pragma unroll
        for (int j = 0; j < N_Q; j++) {
            float v = acc[r][j];
            v += __shfl_xor_sync(0xFFFFFFFFu, v, 16);
            v += __shfl_xor_sync(0xFFFFFFFFu, v, 8);
            v += __shfl_xor_sync(0xFFFFFFFFu, v, 4);
            v += __shfl_xor_sync(0xFFFFFFFFu, v, 2);
            v += __shfl_xor_sync(0xFFFFFFFFu, v, 1);
            if (lane == r * N_Q + j) val = v;
        }

    if (lane < RPW * N_Q && row0 * N_Q + lane < B * N_Q)
        g_pre[(size_t)row0 * N_Q + lane] = val;   // 64B coalesced store
}

// ---------------------------------------------------------------------------
// Kernel 2: per-row 4-qubit circuit + head  (all 32 lanes active)
// ---------------------------------------------------------------------------
__global__ void __launch_bounds__(256) circuit_kernel(
    const float* __restrict__ pre_b,
    const float* __restrict__ u3p,
    const float* __restrict__ post_w,
    const float* __restrict__ post_b,
    float* __restrict__ out,
    int B)
{
    const int row = blockIdx.x * blockDim.x + threadIdx.x;
    if (row >= B) return;

    float4 f = reinterpret_cast<const float4*>(g_pre)[row];
    float fin[N_Q] = {f.x, f.y, f.z, f.w};

    float ry[N_Q], rz[N_Q];
    #pragma unroll
    for (int k = 0; k < N_Q; k++) {
        float p = (fin[k] + __ldg(&pre_b[k])) * 0.1f;
        float t;
        asm("tanh.approx.f32 %0, %1;" : "=f"(t) : "f"(p));
        float qin = t * 1.57079632679489662f;
        ry[k] = atanf(qin);
        rz[k] = atanf(qin * qin);
    }

    // H on |0000>: uniform 1/4 real; RY layer keeps state real
    float r[DIM];
    #pragma unroll
    for (int i = 0; i < DIM; i++) r[i] = 0.25f;
    #pragma unroll
    for (int q = 0; q < N_Q; q++) {
        float s, c;
        __sincosf(0.5f * ry[q], &s, &c);
        const int m = 8 >> q;   // q=0 is MSB
        #pragma unroll
        for (int xx = 0; xx < DIM; xx++) {
            if (!(xx & m)) {
                float a = r[xx], b = r[xx | m];
                r[xx]     = c * a - s * b;
                r[xx | m] = s * a + c * b;
            }
        }
    }

    // RZ: 16 phases via recursive doubling of 4 half-angle exponentials.
    // Index construction: idx = ((q0*2+q1)*2+q2)*2+q3 = q0<<3|q1<<2|q2<<1|q3,
    // which matches the reference bit order (qubit 0 = MSB) directly.
    float pr[DIM], pi[DIM];
    pr[0] = 1.f; pi[0] = 0.f;
    #pragma unroll
    for (int q = 0; q < N_Q; q++) {
        float ss, cc;
        __sincosf(0.5f * rz[q], &ss, &cc);
        const int n = 1 << q;
        #pragma unroll
        for (int t = n - 1; t >= 0; t--) {
            float a = pr[t], b = pi[t];
            pr[2 * t + 1] = a * cc - b * ss;   // bit = 1: *(cc + i ss)
            pi[2 * t + 1] = a * ss + b * cc;
            pr[2 * t]     = a * cc + b * ss;   // bit = 0: *(cc - i ss)
            pi[2 * t]     = b * cc - a * ss;
        }
    }
    float re[DIM], im[DIM];
    #pragma unroll
    for (int xx = 0; xx < DIM; xx++) {
        re[xx] = r[xx] * pr[xx];
        im[xx] = r[xx] * pi[xx];
    }

    // CNOT rings: compile-time permutation
    #define DO_CNOT(cq, tq) { \
        const int cm = 8 >> (cq), tm = 8 >> (tq); \
        _Pragma("unroll") \
        for (int xx = 0; xx < DIM; xx++) { \
            if ((xx & cm) && !(xx & tm)) { \
                int yy = xx ^ tm; \
                float t0 = re[xx]; re[xx] = re[yy]; re[yy] = t0; \
                float t1 = im[xx]; im[xx] = im[yy]; im[yy] = t1; \
            } \
        } }
    DO_CNOT(0, 1); DO_CNOT(1, 2); DO_CNOT(2, 3); DO_CNOT(3, 0);
    DO_CNOT(0, 2); DO_CNOT(1, 3); DO_CNOT(2, 0); DO_CNOT(3, 1);
    #undef DO_CNOT

    // U3 layer
    #pragma unroll
    for (int q = 0; q < N_Q; q++) {
        float th = __ldg(&u3p[q * 3 + 0]);
        float ph = __ldg(&u3p[q * 3 + 1]);
        float la = __ldg(&u3p[q * 3 + 2]);
        float st, ct; __sincosf(0.5f * th, &st, &ct);
        float sl, cl; __sincosf(la, &sl, &cl);
        float sf, cf; __sincosf(ph, &sf, &cf);
        float cpl = cf * cl - sf * sl, spl = sf * cl + cf * sl;
        float m01r = -cl * st, m01i = -sl * st;
        float m10r =  cf * st, m10i =  sf * st;
        float m11r = cpl * ct, m11i = spl * ct;
        const int m = 8 >> q;
        #pragma unroll
        for (int xx = 0; xx < DIM; xx++) {
            if (!(xx & m)) {
                int yy = xx | m;
                float ar = re[xx], ai = im[xx];
                float br = re[yy], bi = im[yy];
                re[xx] = ct * ar + m01r * br - m01i * bi;
                im[xx] = ct * ai + m01r * bi + m01i * br;
                re[yy] = m10r * ar - m10i * ai + m11r * br - m11i * bi;
                im[yy] = m10i * ar + m10r * ai + m11i * br + m11r * bi;
            }
        }
    }

    // Z expectations + head
    float e[N_Q] = {0.f, 0.f, 0.f, 0.f};
    #pragma unroll
    for (int xx = 0; xx < DIM; xx++) {
        float p = re[xx] * re[xx] + im[xx] * im[xx];
        #pragma unroll
        for (int q = 0; q < N_Q; q++)
            e[q] += ((xx >> (3 - q)) & 1) ? -p : p;
    }
    float o0 = __ldg(&post_b[0]);
    float o1 = __ldg(&post_b[1]);
    #pragma unroll
    for (int k = 0; k < N_Q; k++) {
        o0 += e[k] * __ldg(&post_w[k]);
        o1 += e[k] * __ldg(&post_w[N_Q + k]);
    }
    reinterpret_cast<float2*>(out)[row] = make_float2(o0, o1);
}

extern "C" void kernel_launch(void* const* d_in, const int* in_sizes, int n_in,
                              void* d_out, int out_size)
{
    const float* x      = (const float*)d_in[0];
    const float* pre_w  = (const float*)d_in[1];
    const float* pre_b  = (const float*)d_in[2];
    const float* u3p    = (const float*)d_in[3];
    const float* post_w = (const float*)d_in[4];
    const float* post_b = (const float*)d_in[5];
    float* out = (float*)d_out;

    int B = in_sizes[0] / COLS;
    if (B > MAXB) B = MAXB;

    int warps = (B + RPW - 1) / RPW;
    int grid1 = (warps * 32 + BLOCK - 1) / BLOCK;
    gemv_kernel<<<grid1, BLOCK>>>(x, pre_w, B);

    int grid2 = (B + 255) / 256;
    circuit_kernel<<<grid2, 256>>>(pre_b, u3p, post_w, post_b, out, B);
}

// round 14
// speedup vs baseline: 1.3662x; 1.0019x over previous
#include <cuda_runtime.h>

#define N_Q    4
#define DIM    16
#define COLS   512
#define MAXB   32768
#define RPW    4          // rows per warp (GEMV)
#define BLOCK  256

__device__ float g_pre[MAXB * N_Q];   // GEMV output scratch [B,4]
__device__ float g_gate[N_Q][8];      // precomputed U3: ct, m01r, m01i, m10r, m10i, m11r, m11i

// ---------------------------------------------------------------------------
// Kernel 1: GEMV  pre[B,4] = x[B,512] @ pre_w[4,512]^T  (+ block 0 precomputes U3)
// ---------------------------------------------------------------------------
__global__ void __launch_bounds__(BLOCK) gemv_kernel(
    const float* __restrict__ x,
    const float* __restrict__ pre_w,
    const float* __restrict__ u3p,
    int B)
{
    __shared__ float4 wsh[N_Q * (COLS / 4)];   // 8 KB

    const int tid = threadIdx.x;

    // block 0, threads 0..3: precompute U3 gate matrices (precise math, once)
    if (blockIdx.x == 0 && tid < N_Q) {
        float th = u3p[tid * 3 + 0];
        float ph = u3p[tid * 3 + 1];
        float la = u3p[tid * 3 + 2];
        float st, ct; sincosf(0.5f * th, &st, &ct);
        float sl, cl; sincosf(la, &sl, &cl);
        float sf, cf; sincosf(ph, &sf, &cf);
        g_gate[tid][0] = ct;
        g_gate[tid][1] = -cl * st;                      // m01r
        g_gate[tid][2] = -sl * st;                      // m01i
        g_gate[tid][3] =  cf * st;                      // m10r
        g_gate[tid][4] =  sf * st;                      // m10i
        g_gate[tid][5] = (cf * cl - sf * sl) * ct;      // m11r
        g_gate[tid][6] = (sf * cl + cf * sl) * ct;      // m11i
    }

    #pragma unroll
    for (int i = tid; i < N_Q * (COLS / 4); i += BLOCK)
        wsh[i] = reinterpret_cast<const float4*>(pre_w)[i];
    __syncthreads();

    const int warp = (blockIdx.x * BLOCK + tid) >> 5;
    const int lane = tid & 31;
    const int row0 = warp * RPW;
    if (row0 >= B) return;

    const float4* __restrict__ x4 = reinterpret_cast<const float4*>(x);

    float acc[RPW][N_Q];
    #pragma unroll
    for (int r = 0; r < RPW; r++)
        #pragma unroll
        for (int j = 0; j < N_Q; j++) acc[r][j] = 0.f;

    #pragma unroll
    for (int k = 0; k < 4; k++) {
        const int c4 = lane + 32 * k;
        float4 xv[RPW];
        #pragma unroll
        for (int r = 0; r < RPW; r++) {
            int gr = row0 + r;
            xv[r] = x4[(size_t)(gr < B ? gr : B - 1) * 128 + c4];
        }
        float4 w0 = wsh[0 * 128 + c4];
        float4 w1 = wsh[1 * 128 + c4];
        float4 w2 = wsh[2 * 128 + c4];
        float4 w3 = wsh[3 * 128 + c4];
        #pragma unroll
        for (int r = 0; r < RPW; r++) {
            acc[r][0] += xv[r].x * w0.x + xv[r].y * w0.y + xv[r].z * w0.z + xv[r].w * w0.w;
            acc[r][1] += xv[r].x * w1.x + xv[r].y * w1.y + xv[r].z * w1.z + xv[r].w * w1.w;
            acc[r][2] += xv[r].x * w2.x + xv[r].y * w2.y + xv[r].z * w2.z + xv[r].w * w2.w;
            acc[r][3] += xv[r].x * w3.x + xv[r].y * w3.y + xv[r].z * w3.z + xv[r].w * w3.w;
        }
    }

    float val = 0.f;
    #pragma unroll
    for (int r = 0; r < RPW; r++)
        #pragma unroll
        for (int j = 0; j < N_Q; j++) {
            float v = acc[r][j];
            v += __shfl_xor_sync(0xFFFFFFFFu, v, 16);
            v += __shfl_xor_sync(0xFFFFFFFFu, v, 8);
            v += __shfl_xor_sync(0xFFFFFFFFu, v, 4);
            v += __shfl_xor_sync(0xFFFFFFFFu, v, 2);
            v += __shfl_xor_sync(0xFFFFFFFFu, v, 1);
            if (lane == r * N_Q + j) val = v;
        }

    if (lane < RPW * N_Q && row0 * N_Q + lane < B * N_Q)
        g_pre[(size_t)row0 * N_Q + lane] = val;
}

// ---------------------------------------------------------------------------
// fast atan: branchless minimax, |err| < ~1e-5 rad
// ---------------------------------------------------------------------------
__device__ __forceinline__ float fast_atan(float x)
{
    float a   = fabsf(x);
    bool  inv = a > 1.0f;
    float z   = inv ? __fdividef(1.0f, a) : a;
    float z2  = z * z;
    float p   = -0.0117212f;
    p = fmaf(p, z2,  0.05265332f);
    p = fmaf(p, z2, -0.11643287f);
    p = fmaf(p, z2,  0.19354346f);
    p = fmaf(p, z2, -0.33262347f);
    p = fmaf(p, z2,  0.99997726f);
    p = p * z;
    float r = inv ? (1.57079632679489662f - p) : p;
    return copysignf(r, x);
}

// ---------------------------------------------------------------------------
// Kernel 2: per-row 4-qubit circuit + head
// ---------------------------------------------------------------------------
__global__ void __launch_bounds__(128) circuit_kernel(
    const float* __restrict__ pre_b,
    const float* __restrict__ post_w,
    const float* __restrict__ post_b,
    float* __restrict__ out,
    int B)
{
    const int row = blockIdx.x * blockDim.x + threadIdx.x;
    if (row >= B) return;

    float4 f = reinterpret_cast<const float4*>(g_pre)[row];
    float fin[N_Q] = {f.x, f.y, f.z, f.w};

    float ry[N_Q], rz[N_Q];
    #pragma unroll
    for (int k = 0; k < N_Q; k++) {
        float p = (fin[k] + __ldg(&pre_b[k])) * 0.1f;
        float t;
        asm("tanh.approx.f32 %0, %1;" : "=f"(t) : "f"(p));
        float qin = t * 1.57079632679489662f;
        ry[k] = fast_atan(qin);
        rz[k] = fast_atan(qin * qin);
    }

    // H on |0000>: uniform 1/4 real; RY layer keeps state real
    float r[DIM];
    #pragma unroll
    for (int i = 0; i < DIM; i++) r[i] = 0.25f;
    #pragma unroll
    for (int q = 0; q < N_Q; q++) {
        float s, c;
        __sincosf(0.5f * ry[q], &s, &c);
        const int m = 8 >> q;   // q=0 is MSB
        #pragma unroll
        for (int xx = 0; xx < DIM; xx++) {
            if (!(xx & m)) {
                float a = r[xx], b = r[xx | m];
                r[xx]     = c * a - s * b;
                r[xx | m] = s * a + c * b;
            }
        }
    }

    // RZ: recursive doubling; idx = q0<<3|q1<<2|q2<<1|q3 matches reference order
    float pr[DIM], pi[DIM];
    pr[0] = 1.f; pi[0] = 0.f;
    #pragma unroll
    for (int q = 0; q < N_Q; q++) {
        float ss, cc;
        __sincosf(0.5f * rz[q], &ss, &cc);
        const int n = 1 << q;
        #pragma unroll
        for (int t = n - 1; t >= 0; t--) {
            float a = pr[t], b = pi[t];
            pr[2 * t + 1] = a * cc - b * ss;
            pi[2 * t + 1] = a * ss + b * cc;
            pr[2 * t]     = a * cc + b * ss;
            pi[2 * t]     = b * cc - a * ss;
        }
    }
    float re[DIM], im[DIM];
    #pragma unroll
    for (int xx = 0; xx < DIM; xx++) {
        re[xx] = r[xx] * pr[xx];
        im[xx] = r[xx] * pi[xx];
    }

    // CNOT rings: compile-time permutation
    #define DO_CNOT(cq, tq) { \
        const int cm = 8 >> (cq), tm = 8 >> (tq); \
        _Pragma("unroll") \
        for (int xx = 0; xx < DIM; xx++) { \
            if ((xx & cm) && !(xx & tm)) { \
                int yy = xx ^ tm; \
                float t0 = re[xx]; re[xx] = re[yy]; re[yy] = t0; \
                float t1 = im[xx]; im[xx] = im[yy]; im[yy] = t1; \
            } \
        } }
    DO_CNOT(0, 1); DO_CNOT(1, 2); DO_CNOT(2, 3); DO_CNOT(3, 0);
    DO_CNOT(0, 2); DO_CNOT(1, 3); DO_CNOT(2, 0); DO_CNOT(3, 1);
    #undef DO_CNOT

    // U3 layer: precomputed gate constants (broadcast loads)
    #pragma unroll
    for (int q = 0; q < N_Q; q++) {
        float ct   = g_gate[q][0];
        float m01r = g_gate[q][1], m01i = g_gate[q][2];
        float m10r = g_gate[q][3], m10i = g_gate[q][4];
        float m11r = g_gate[q][5], m11i = g_gate[q][6];
        const int m = 8 >> q;
        #pragma unroll
        for (int xx = 0; xx < DIM; xx++) {
            if (!(xx & m)) {
                int yy = xx | m;
                float ar = re[xx], ai = im[xx];
                float br = re[yy], bi = im[yy];
                re[xx] = ct * ar + m01r * br - m01i * bi;
                im[xx] = ct * ai + m01r * bi + m01i * br;
                re[yy] = m10r * ar - m10i * ai + m11r * br - m11i * bi;
                im[yy] = m10i * ar + m10r * ai + m11i * br + m11r * bi;
            }
        }
    }

    // Z expectations + head
    float e[N_Q] = {0.f, 0.f, 0.f, 0.f};
    #pragma unroll
    for (int xx = 0; xx < DIM; xx++) {
        float p = re[xx] * re[xx] + im[xx] * im[xx];
        #pragma unroll
        for (int q = 0; q < N_Q; q++)
            e[q] += ((xx >> (3 - q)) & 1) ? -p : p;
    }
    float o0 = __ldg(&post_b[0]);
    float o1 = __ldg(&post_b[1]);
    #pragma unroll
    for (int k = 0; k < N_Q; k++) {
        o0 += e[k] * __ldg(&post_w[k]);
        o1 += e[k] * __ldg(&post_w[N_Q + k]);
    }
    reinterpret_cast<float2*>(out)[row] = make_float2(o0, o1);
}

extern "C" void kernel_launch(void* const* d_in, const int* in_sizes, int n_in,
                              void* d_out, int out_size)
{
    const float* x      = (const float*)d_in[0];
    const float* pre_w  = (const float*)d_in[1];
    const float* pre_b  = (const float*)d_in[2];
    const float* u3p    = (const float*)d_in[3];
    const float* post_w = (const float*)d_in[4];
    const float* post_b = (const float*)d_in[5];
    float* out = (float*)d_out;

    int B = in_sizes[0] / COLS;
    if (B > MAXB) B = MAXB;

    int warps = (B + RPW - 1) / RPW;
    int grid1 = (warps * 32 + BLOCK - 1) / BLOCK;
    gemv_kernel<<<grid1, BLOCK>>>(x, pre_w, u3p, B);

    int grid2 = (B + 127) / 128;
    circuit_kernel<<<grid2, 128>>>(pre_b, post_w, post_b, out, B);
}

// round 15
// speedup vs baseline: 1.5584x; 1.1407x over previous
#include <cuda_runtime.h>

#define N_Q    4
#define DIM    16
#define COLS   512
#define MAXB   32768
#define RPW    4          // rows per warp (GEMV)
#define BLOCK  256

__device__ float g_pre[MAXB * N_Q];   // GEMV output scratch [B,4]
__device__ float g_gate[N_Q][8];      // U3: ct, m01r, m01i, m10r, m10i, m11r, m11i

// ---------------------------------------------------------------------------
// Kernel 1: GEMV  pre[B,4] = x[B,512] @ pre_w[4,512]^T  (+ block 0 precomputes U3)
// ---------------------------------------------------------------------------
__global__ void __launch_bounds__(BLOCK) gemv_kernel(
    const float* __restrict__ x,
    const float* __restrict__ pre_w,
    const float* __restrict__ u3p,
    int B)
{
    __shared__ float4 wsh[N_Q * (COLS / 4)];   // 8 KB

    const int tid = threadIdx.x;

    if (blockIdx.x == 0 && tid < N_Q) {
        float th = u3p[tid * 3 + 0];
        float ph = u3p[tid * 3 + 1];
        float la = u3p[tid * 3 + 2];
        float st, ct; sincosf(0.5f * th, &st, &ct);
        float sl, cl; sincosf(la, &sl, &cl);
        float sf, cf; sincosf(ph, &sf, &cf);
        g_gate[tid][0] = ct;
        g_gate[tid][1] = -cl * st;                 // m01r
        g_gate[tid][2] = -sl * st;                 // m01i
        g_gate[tid][3] =  cf * st;                 // m10r
        g_gate[tid][4] =  sf * st;                 // m10i
        g_gate[tid][5] = (cf * cl - sf * sl) * ct; // m11r
        g_gate[tid][6] = (sf * cl + cf * sl) * ct; // m11i
    }

    #pragma unroll
    for (int i = tid; i < N_Q * (COLS / 4); i += BLOCK)
        wsh[i] = reinterpret_cast<const float4*>(pre_w)[i];
    __syncthreads();

    const int warp = (blockIdx.x * BLOCK + tid) >> 5;
    const int lane = tid & 31;
    const int row0 = warp * RPW;
    if (row0 >= B) return;

    const float4* __restrict__ x4 = reinterpret_cast<const float4*>(x);

    float acc[RPW][N_Q];
    #pragma unroll
    for (int r = 0; r < RPW; r++)
        #pragma unroll
        for (int j = 0; j < N_Q; j++) acc[r][j] = 0.f;

    #pragma unroll
    for (int k = 0; k < 4; k++) {
        const int c4 = lane + 32 * k;
        float4 xv[RPW];
        #pragma unroll
        for (int r = 0; r < RPW; r++) {
            int gr = row0 + r;
            xv[r] = x4[(size_t)(gr < B ? gr : B - 1) * 128 + c4];
        }
        float4 w0 = wsh[0 * 128 + c4];
        float4 w1 = wsh[1 * 128 + c4];
        float4 w2 = wsh[2 * 128 + c4];
        float4 w3 = wsh[3 * 128 + c4];
        #pragma unroll
        for (int r = 0; r < RPW; r++) {
            acc[r][0] += xv[r].x * w0.x + xv[r].y * w0.y + xv[r].z * w0.z + xv[r].w * w0.w;
            acc[r][1] += xv[r].x * w1.x + xv[r].y * w1.y + xv[r].z * w1.z + xv[r].w * w1.w;
            acc[r][2] += xv[r].x * w2.x + xv[r].y * w2.y + xv[r].z * w2.z + xv[r].w * w2.w;
            acc[r][3] += xv[r].x * w3.x + xv[r].y * w3.y + xv[r].z * w3.z + xv[r].w * w3.w;
        }
    }

    float val = 0.f;
    #pragma unroll
    for (int r = 0; r < RPW; r++)
        #pragma unroll
        for (int j = 0; j < N_Q; j++) {
            float v = acc[r][j];
            v += __shfl_xor_sync(0xFFFFFFFFu, v, 16);
            v += __shfl_xor_sync(0xFFFFFFFFu, v, 8);
            v += __shfl_xor_sync(0xFFFFFFFFu, v, 4);
            v += __shfl_xor_sync(0xFFFFFFFFu, v, 2);
            v += __shfl_xor_sync(0xFFFFFFFFu, v, 1);
            if (lane == r * N_Q + j) val = v;
        }

    if (lane < RPW * N_Q && row0 * N_Q + lane < B * N_Q)
        g_pre[(size_t)row0 * N_Q + lane] = val;
}

// ---------------------------------------------------------------------------
__device__ __forceinline__ float fast_atan(float x)
{
    float a   = fabsf(x);
    bool  inv = a > 1.0f;
    float z   = inv ? __fdividef(1.0f, a) : a;
    float z2  = z * z;
    float p   = -0.0117212f;
    p = fmaf(p, z2,  0.05265332f);
    p = fmaf(p, z2, -0.11643287f);
    p = fmaf(p, z2,  0.19354346f);
    p = fmaf(p, z2, -0.33262347f);
    p = fmaf(p, z2,  0.99997726f);
    p = p * z;
    float r = inv ? (1.57079632679489662f - p) : p;
    return copysignf(r, x);
}

#define SHX(v) __shfl_xor_sync(0xFFFFFFFFu, (v), 1)

// ---------------------------------------------------------------------------
// Kernel 2: circuit, 2 lanes per row. Lane parity p owns amplitudes with
// qubit-0 bit (MSB of state index) == p; local index i = xx & 7.
// ---------------------------------------------------------------------------
__global__ void __launch_bounds__(128) circuit_kernel(
    const float* __restrict__ pre_b,
    const float* __restrict__ post_w,
    const float* __restrict__ post_b,
    float* __restrict__ out,
    int B)
{
    const int gtid = blockIdx.x * blockDim.x + threadIdx.x;
    const int row  = gtid >> 1;
    if (row >= B) return;
    const int p = gtid & 1;

    float4 f = reinterpret_cast<const float4*>(g_pre)[row];
    float fin[N_Q] = {f.x, f.y, f.z, f.w};

    float ry[N_Q], rz[N_Q];
    #pragma unroll
    for (int k = 0; k < N_Q; k++) {
        float pp = (fin[k] + __ldg(&pre_b[k])) * 0.1f;
        float t;
        asm("tanh.approx.f32 %0, %1;" : "=f"(t) : "f"(pp));
        float qin = t * 1.57079632679489662f;
        ry[k] = fast_atan(qin);
        rz[k] = fast_atan(qin * qin);
    }

    // ---- H|0000> = uniform 0.25 real, then RY layer (state stays real) ----
    float r[8];
    #pragma unroll
    for (int i = 0; i < 8; i++) r[i] = 0.25f;

    // RY qubit 0 (cross-lane): pair (lane0.i, lane1.i)
    {
        float s, c;
        __sincosf(0.5f * ry[0], &s, &c);
        float se = p ? s : -s;   // lane0: c*a - s*b ; lane1: c*b + s*a
        #pragma unroll
        for (int i = 0; i < 8; i++) {
            float rp = SHX(r[i]);
            r[i] = fmaf(se, rp, c * r[i]);
        }
    }
    // RY qubits 1..3 (local): m = 4 >> (q-1)
    #pragma unroll
    for (int q = 1; q < N_Q; q++) {
        float s, c;
        __sincosf(0.5f * ry[q], &s, &c);
        const int m = 4 >> (q - 1);
        #pragma unroll
        for (int i = 0; i < 8; i++) {
            if (!(i & m)) {
                float a = r[i], b = r[i | m];
                r[i]     = c * a - s * b;
                r[i | m] = s * a + c * b;
            }
        }
    }

    // ---- RZ (diagonal, lane-local): phase(xx) seeded with qubit-0 sign ----
    float pr[8], pi[8];
    {
        float ss0, cc0;
        __sincosf(0.5f * rz[0], &ss0, &cc0);
        pr[0] = cc0;
        pi[0] = p ? ss0 : -ss0;
    }
    #pragma unroll
    for (int q = 1; q < N_Q; q++) {
        float ss, cc;
        __sincosf(0.5f * rz[q], &ss, &cc);
        const int n = 1 << (q - 1);
        #pragma unroll
        for (int t = n - 1; t >= 0; t--) {
            float a = pr[t], b = pi[t];
            pr[2 * t + 1] = a * cc - b * ss;   // bit = 1: *(cc + i ss)
            pi[2 * t + 1] = a * ss + b * cc;
            pr[2 * t]     = a * cc + b * ss;   // bit = 0: *(cc - i ss)
            pi[2 * t]     = b * cc - a * ss;
        }
    }
    float re[8], im[8];
    #pragma unroll
    for (int i = 0; i < 8; i++) {
        re[i] = r[i] * pr[i];
        im[i] = r[i] * pi[i];
    }

    // ---- all 8 CNOTs composed: new[y] = old[P[y]],
    //      P = [0,6,12,10,11,13,7,1,15,9,3,5,4,2,8,14]
    //      crossing locals {2,3,4,5} exchanged symmetrically via shfl_xor(1)
    {
        float xr2 = SHX(re[2]), xi2 = SHX(im[2]);
        float xr3 = SHX(re[3]), xi3 = SHX(im[3]);
        float xr4 = SHX(re[4]), xi4 = SHX(im[4]);
        float xr5 = SHX(re[5]), xi5 = SHX(im[5]);
        float o0r = re[0], o0i = im[0], o1r = re[1], o1i = im[1];
        float o6r = re[6], o6i = im[6], o7r = re[7], o7i = im[7];
        if (p == 0) {
            re[0] = o0r; im[0] = o0i;         // old 0
            re[1] = o6r; im[1] = o6i;         // old 6
            re[2] = xr4; im[2] = xi4;         // old 12
            re[3] = xr2; im[3] = xi2;         // old 10
            re[4] = xr3; im[4] = xi3;         // old 11
            re[5] = xr5; im[5] = xi5;         // old 13
            re[6] = o7r; im[6] = o7i;         // old 7
            re[7] = o1r; im[7] = o1i;         // old 1
        } else {
            re[0] = o7r; im[0] = o7i;         // new8  = old 15
            re[1] = o1r; im[1] = o1i;         // new9  = old 9
            re[2] = xr3; im[2] = xi3;         // new10 = old 3
            re[3] = xr5; im[3] = xi5;         // new11 = old 5
            re[4] = xr4; im[4] = xi4;         // new12 = old 4
            re[5] = xr2; im[5] = xi2;         // new13 = old 2
            re[6] = o0r; im[6] = o0i;         // new14 = old 0
            re[7] = o6r; im[7] = o6i;         // new15 = old 6
        }
    }

    // ---- U3 qubit 0 (cross-lane): n = alpha*v + beta*w,  w = partner ----
    {
        float ct   = g_gate[0][0];
        float m01r = g_gate[0][1], m01i = g_gate[0][2];
        float m10r = g_gate[0][3], m10i = g_gate[0][4];
        float m11r = g_gate[0][5], m11i = g_gate[0][6];
        float ar = p ? m11r : ct;
        float ai = p ? m11i : 0.f;
        float br = p ? m10r : m01r;
        float bi = p ? m10i : m01i;
        #pragma unroll
        for (int i = 0; i < 8; i++) {
            float wr = SHX(re[i]);
            float wi = SHX(im[i]);
            float vr = re[i], vi = im[i];
            re[i] = ar * vr - ai * vi + br * wr - bi * wi;
            im[i] = ar * vi + ai * vr + br * wi + bi * wr;
        }
    }
    // ---- U3 qubits 1..3 (local) ----
    #pragma unroll
    for (int q = 1; q < N_Q; q++) {
        float ct   = g_gate[q][0];
        float m01r = g_gate[q][1], m01i = g_gate[q][2];
        float m10r = g_gate[q][3], m10i = g_gate[q][4];
        float m11r = g_gate[q][5], m11i = g_gate[q][6];
        const int m = 4 >> (q - 1);
        #pragma unroll
        for (int i = 0; i < 8; i++) {
            if (!(i & m)) {
                int j = i | m;
                float a_r = re[i], a_i = im[i];
                float b_r = re[j], b_i = im[j];
                re[i] = ct * a_r + m01r * b_r - m01i * b_i;
                im[i] = ct * a_i + m01r * b_i + m01i * b_r;
                re[j] = m10r * a_r - m10i * a_i + m11r * b_r - m11i * b_i;
                im[j] = m10i * a_r + m10r * a_i + m11i * b_r + m11r * b_i;
            }
        }
    }

    // ---- Z expectations: local partials, then cross-lane add ----
    float e[N_Q] = {0.f, 0.f, 0.f, 0.f};
    #pragma unroll
    for (int i = 0; i < 8; i++) {
        float pp = re[i] * re[i] + im[i] * im[i];
        e[0] += pp;                          // sign applied below (qubit0 = lane bit)
        e[1] += (i & 4) ? -pp : pp;
        e[2] += (i & 2) ? -pp : pp;
        e[3] += (i & 1) ? -pp : pp;
    }
    e[0] = p ? -e[0] : e[0];
    #pragma unroll
    for (int q = 0; q < N_Q; q++)
        e[q] += SHX(e[q]);

    // even lane writes o0, odd lane writes o1 -> fully coalesced
    float o = __ldg(&post_b[p]);
    #pragma unroll
    for (int k = 0; k < N_Q; k++)
        o += e[k] * __ldg(&post_w[p * N_Q + k]);
    out[2 * (size_t)row + p] = o;
}

extern "C" void kernel_launch(void* const* d_in, const int* in_sizes, int n_in,
                              void* d_out, int out_size)
{
    const float* x      = (const float*)d_in[0];
    const float* pre_w  = (const float*)d_in[1];
    const float* pre_b  = (const float*)d_in[2];
    const float* u3p    = (const float*)d_in[3];
    const float* post_w = (const float*)d_in[4];
    const float* post_b = (const float*)d_in[5];
    float* out = (float*)d_out;

    int B = in_sizes[0] / COLS;
    if (B > MAXB) B = MAXB;

    int warps = (B + RPW - 1) / RPW;
    int grid1 = (warps * 32 + BLOCK - 1) / BLOCK;
    gemv_kernel<<<grid1, BLOCK>>>(x, pre_w, u3p, B);

    int grid2 = (2 * B + 127) / 128;
    circuit_kernel<<<grid2, 128>>>(pre_b, post_w, post_b, out, B);
}